// round 1
// baseline (speedup 1.0000x reference)
#include <cuda_runtime.h>
#include <math.h>

#define NTOT 16384      // B*Q
#define DDIM 256
#define KCB  8192
#define GATHER_BLOCKS 4096

#define LOSS_OFF (NTOT*DDIM)              // 4194304
#define IDX_OFF  (NTOT*DDIM + 1)          // 4194305
#define PPL_OFF  (NTOT*DDIM + 1 + NTOT)   // 4210689
#define OUT_FULL (NTOT*DDIM + 2 + NTOT)   // 4210690

__device__ float g_e2[KCB];
__device__ int   g_idx[NTOT];
__device__ float g_partial[GATHER_BLOCKS];

// ---------------------------------------------------------------------------
// Kernel 1: codebook squared norms (warp per code)
// ---------------------------------------------------------------------------
__global__ void vq_e2_kernel(const float* __restrict__ cb) {
    int w    = (blockIdx.x * blockDim.x + threadIdx.x) >> 5;
    int lane = threadIdx.x & 31;
    if (w >= KCB) return;
    const float4* p = (const float4*)(cb + (size_t)w * DDIM);
    float s = 0.f;
#pragma unroll
    for (int i = 0; i < 2; i++) {
        float4 v = p[lane + i * 32];
        s += v.x * v.x + v.y * v.y + v.z * v.z + v.w * v.w;
    }
#pragma unroll
    for (int o = 16; o > 0; o >>= 1) s += __shfl_down_sync(0xffffffffu, s, o);
    if (lane == 0) g_e2[w] = s;
}

// ---------------------------------------------------------------------------
// Kernel 2: fused GEMM + argmin.  dist(n,k) = e2[k] - 2 * dot(z[n], cb[k])
// Block: 128 rows x full K loop (chunks of 128 codes), 256 threads, 8x8 tiles.
// ---------------------------------------------------------------------------
#define BM 128
#define BK 128
#define DC 32

__global__ void __launch_bounds__(256, 1)
vq_argmin_kernel(const float* __restrict__ z, const float* __restrict__ cb) {
    __shared__ float zs[DC * BM];   // [dd][row]  16 KB
    __shared__ float cs[DC * BK];   // [dd][code] 16 KB

    const int t  = threadIdx.x;
    const int tx = t & 15;          // code group 0..15  (8 codes each)
    const int ty = t >> 4;          // row  group 0..15  (8 rows each)
    const int m0 = blockIdx.x * BM;

    const int lr = t >> 1;          // load row 0..127
    const int lc = (t & 1) * 16;    // load col base 0 or 16

    float bestd[8];
    int   besti[8];
#pragma unroll
    for (int i = 0; i < 8; i++) { bestd[i] = 3.0e38f; besti[i] = 0; }

    for (int kc = 0; kc < KCB; kc += BK) {
        float acc[8][8];
#pragma unroll
        for (int i = 0; i < 8; i++)
#pragma unroll
            for (int j = 0; j < 8; j++) acc[i][j] = 0.f;

        for (int d0 = 0; d0 < DDIM; d0 += DC) {
            // Load + transpose tiles into smem
            const float* zp = z  + (size_t)(m0 + lr) * DDIM + d0 + lc;
            const float* cp = cb + (size_t)(kc + lr) * DDIM + d0 + lc;
#pragma unroll
            for (int v = 0; v < 4; v++) {
                float4 a = *(const float4*)(zp + v * 4);
                float4 b = *(const float4*)(cp + v * 4);
                int dbase = lc + v * 4;
                zs[(dbase + 0) * BM + lr] = a.x;
                zs[(dbase + 1) * BM + lr] = a.y;
                zs[(dbase + 2) * BM + lr] = a.z;
                zs[(dbase + 3) * BM + lr] = a.w;
                cs[(dbase + 0) * BK + lr] = b.x;
                cs[(dbase + 1) * BK + lr] = b.y;
                cs[(dbase + 2) * BK + lr] = b.z;
                cs[(dbase + 3) * BK + lr] = b.w;
            }
            __syncthreads();

#pragma unroll 8
            for (int dd = 0; dd < DC; dd++) {
                const float4* z4 = (const float4*)(zs + dd * BM + (ty << 3));
                const float4* c4 = (const float4*)(cs + dd * BK + (tx << 3));
                float4 a0 = z4[0], a1 = z4[1];
                float4 b0 = c4[0], b1 = c4[1];
                float av[8] = {a0.x, a0.y, a0.z, a0.w, a1.x, a1.y, a1.z, a1.w};
                float bv[8] = {b0.x, b0.y, b0.z, b0.w, b1.x, b1.y, b1.z, b1.w};
#pragma unroll
                for (int i = 0; i < 8; i++)
#pragma unroll
                    for (int j = 0; j < 8; j++)
                        acc[i][j] = fmaf(av[i], bv[j], acc[i][j]);
            }
            __syncthreads();
        }

        // Distance + best update (codes scanned in ascending index order)
#pragma unroll
        for (int j = 0; j < 8; j++) {
            int   code = kc + (tx << 3) + j;
            float e    = g_e2[code];
#pragma unroll
            for (int i = 0; i < 8; i++) {
                float dist = fmaf(-2.f, acc[i][j], e);
                if (dist < bestd[i]) { bestd[i] = dist; besti[i] = code; }
            }
        }
    }

    // Cross-thread (tx) reduction per row, first-index tie-break
    __syncthreads();
    float* sd = zs;            // 128 rows x 16 = 8 KB
    int*   si = (int*)cs;
#pragma unroll
    for (int i = 0; i < 8; i++) {
        int row = (ty << 3) + i;
        sd[row * 16 + tx] = bestd[i];
        si[row * 16 + tx] = besti[i];
    }
    __syncthreads();
    if (t < BM) {
        float bd = sd[t * 16];
        int   bi = si[t * 16];
#pragma unroll
        for (int x = 1; x < 16; x++) {
            float d = sd[t * 16 + x];
            int   ii = si[t * 16 + x];
            if (d < bd || (d == bd && ii < bi)) { bd = d; bi = ii; }
        }
        g_idx[m0 + t] = bi;
    }
}

// ---------------------------------------------------------------------------
// Kernel 3: gather z_q, write indices, per-block partial sum of (z_q - z)^2
// ---------------------------------------------------------------------------
__global__ void vq_gather_kernel(const float* __restrict__ z,
                                 const float* __restrict__ cb,
                                 float* __restrict__ out, int out_size) {
    __shared__ float red[256];
    const int t    = threadIdx.x;
    const int base = blockIdx.x * 1024;   // 1024 elems per block
    const int e    = base + t * 4;
    const int row  = e >> 8;
    const int col  = e & 255;
    const int code = g_idx[row];

    float4 q  = *(const float4*)(cb + (size_t)code * DDIM + col);
    float4 zv = *(const float4*)(z + e);
    *(float4*)(out + e) = q;

    if (col == 0 && out_size >= OUT_FULL) out[IDX_OFF + row] = (float)code;

    float dx = q.x - zv.x, dy = q.y - zv.y, dz = q.z - zv.z, dw = q.w - zv.w;
    red[t] = dx * dx + dy * dy + dz * dz + dw * dw;
    __syncthreads();
#pragma unroll
    for (int o = 128; o > 0; o >>= 1) {
        if (t < o) red[t] += red[t + o];
        __syncthreads();
    }
    if (t == 0) g_partial[blockIdx.x] = red[0];
}

// ---------------------------------------------------------------------------
// Kernel 4: finalize vq_loss + perplexity (single block, fixed-order reduce)
// ---------------------------------------------------------------------------
__global__ void vq_finalize_kernel(const float* __restrict__ ema,
                                   float* __restrict__ out, int out_size) {
    __shared__ float r1[256], r2[256];
    const int t = threadIdx.x;

    // loss sum over fixed partial slots
    float s = 0.f;
    for (int i = t; i < GATHER_BLOCKS; i += 256) s += g_partial[i];
    r1[t] = s;
    __syncthreads();
#pragma unroll
    for (int o = 128; o > 0; o >>= 1) {
        if (t < o) r1[t] += r1[t + o];
        __syncthreads();
    }
    if (t == 0 && out_size >= OUT_FULL) {
        float mse = r1[0] / (float)(NTOT * DDIM);
        out[LOSS_OFF] = 1.25f * mse;   // codebook + BETA*commitment (equal values)
    }
    __syncthreads();

    // perplexity: counts with EOP/PAD zeroed, clipped at EPS
    float sc = 0.f, scl = 0.f;
    for (int k = t; k < KCB; k += 256) {
        float c = ema[k];
        if (k == 2 || k == 3) c = 0.f;
        c = fmaxf(c, 1e-5f);
        sc  += c;
        scl += c * logf(c);
    }
    r1[t] = sc; r2[t] = scl;
    __syncthreads();
#pragma unroll
    for (int o = 128; o > 0; o >>= 1) {
        if (t < o) { r1[t] += r1[t + o]; r2[t] += r2[t + o]; }
        __syncthreads();
    }
    if (t == 0 && out_size >= OUT_FULL) {
        float T = r1[0] + 1e-5f;
        // entropy = -(sum p log p), p = c/T  =>  log(T)*(Sc/T) - Sclogc/T
        float entropy = logf(T) * (r1[0] / T) - r2[0] / T;
        out[PPL_OFF] = expf(entropy);
    }
}

// ---------------------------------------------------------------------------
extern "C" void kernel_launch(void* const* d_in, const int* in_sizes, int n_in,
                              void* d_out, int out_size) {
    const float* z   = (const float*)d_in[0];
    const float* cb  = (const float*)d_in[1];
    const float* ema = (const float*)d_in[2];
    float* out = (float*)d_out;

    vq_e2_kernel<<<KCB * 32 / 256, 256>>>(cb);
    vq_argmin_kernel<<<NTOT / BM, 256>>>(z, cb);
    vq_gather_kernel<<<GATHER_BLOCKS, 256>>>(z, cb, out, out_size);
    vq_finalize_kernel<<<1, 256>>>(ema, out, out_size);
}

// round 4
// speedup vs baseline: 7.1186x; 7.1186x over previous
#include <cuda_runtime.h>
#include <cuda_bf16.h>
#include <math.h>
#include <stdint.h>

#define NTOT 16384
#define DDIM 256
#define KCB  8192
#define NCHUNK 64
#define GATHER_BLOCKS 4096

#define LOSS_OFF (NTOT*DDIM)
#define IDX_OFF  (NTOT*DDIM + 1)
#define PPL_OFF  (NTOT*DDIM + 1 + NTOT)
#define OUT_FULL (NTOT*DDIM + 2 + NTOT)

__device__ __align__(16) __nv_bfloat16 g_z_bf[(size_t)NTOT * DDIM];
__device__ __align__(16) __nv_bfloat16 g_cb_bf[(size_t)KCB * DDIM];
__device__ float g_e2f[KCB];
__device__ int   g_cand[(size_t)NTOT * 32];
__device__ int   g_idx[NTOT];
__device__ float g_partial[GATHER_BLOCKS];

// ---------------------------------------------------------------------------
// helpers
// ---------------------------------------------------------------------------
__device__ __forceinline__ uint32_t smem_u32(const void* p) {
    uint32_t a;
    asm("{ .reg .u64 t; cvta.to.shared.u64 t, %1; cvt.u32.u64 %0, t; }"
        : "=r"(a) : "l"(p));
    return a;
}
#define CP_ASYNC16(dst, src) \
    asm volatile("cp.async.cg.shared.global [%0], [%1], 16;" :: "r"(dst), "l"(src))
#define CP_COMMIT() asm volatile("cp.async.commit_group;" ::: "memory")
#define CP_WAIT(n)  asm volatile("cp.async.wait_group %0;" :: "n"(n) : "memory")

__device__ __forceinline__ void ldsm_x4(uint32_t* r, uint32_t addr) {
    asm volatile("ldmatrix.sync.aligned.m8n8.x4.shared.b16 {%0,%1,%2,%3}, [%4];"
                 : "=r"(r[0]), "=r"(r[1]), "=r"(r[2]), "=r"(r[3]) : "r"(addr));
}
__device__ __forceinline__ void mma16816(float* d, const uint32_t* a,
                                         uint32_t b0, uint32_t b1) {
    asm volatile(
        "mma.sync.aligned.m16n8k16.row.col.f32.bf16.bf16.f32 "
        "{%0,%1,%2,%3}, {%4,%5,%6,%7}, {%8,%9}, {%0,%1,%2,%3};"
        : "+f"(d[0]), "+f"(d[1]), "+f"(d[2]), "+f"(d[3])
        : "r"(a[0]), "r"(a[1]), "r"(a[2]), "r"(a[3]), "r"(b0), "r"(b1));
}
__device__ __forceinline__ void upd(float& b1, int& i1, float& b2, int& i2,
                                    float d, int code) {
    if (d < b2) {
        if (d < b1) { b2 = b1; i2 = i1; b1 = d; i1 = code; }
        else        { b2 = d; i2 = code; }
    }
}

// ---------------------------------------------------------------------------
// Kernel 1: convert z, cb to bf16; exact fp32 e2 per code
// ---------------------------------------------------------------------------
__global__ void vq_convert_kernel(const float* __restrict__ z,
                                  const float* __restrict__ cb) {
    int w    = (blockIdx.x * blockDim.x + threadIdx.x) >> 5;
    int lane = threadIdx.x & 31;
    if (w < KCB) {
        const float4* src = (const float4*)(cb + (size_t)w * DDIM);
        float4 v0 = src[lane * 2], v1 = src[lane * 2 + 1];
        float e2 = v0.x*v0.x + v0.y*v0.y + v0.z*v0.z + v0.w*v0.w
                 + v1.x*v1.x + v1.y*v1.y + v1.z*v1.z + v1.w*v1.w;
        __nv_bfloat162 h0 = __floats2bfloat162_rn(v0.x, v0.y);
        __nv_bfloat162 h1 = __floats2bfloat162_rn(v0.z, v0.w);
        __nv_bfloat162 h2 = __floats2bfloat162_rn(v1.x, v1.y);
        __nv_bfloat162 h3 = __floats2bfloat162_rn(v1.z, v1.w);
        uint4 o;
        o.x = *reinterpret_cast<uint32_t*>(&h0);
        o.y = *reinterpret_cast<uint32_t*>(&h1);
        o.z = *reinterpret_cast<uint32_t*>(&h2);
        o.w = *reinterpret_cast<uint32_t*>(&h3);
        ((uint4*)(g_cb_bf + (size_t)w * DDIM))[lane] = o;
#pragma unroll
        for (int o2 = 16; o2 > 0; o2 >>= 1) e2 += __shfl_down_sync(0xffffffffu, e2, o2);
        if (lane == 0) g_e2f[w] = e2;
    } else if (w < KCB + NTOT) {
        int r = w - KCB;
        const float4* src = (const float4*)(z + (size_t)r * DDIM);
        float4 v0 = src[lane * 2], v1 = src[lane * 2 + 1];
        __nv_bfloat162 h0 = __floats2bfloat162_rn(v0.x, v0.y);
        __nv_bfloat162 h1 = __floats2bfloat162_rn(v0.z, v0.w);
        __nv_bfloat162 h2 = __floats2bfloat162_rn(v1.x, v1.y);
        __nv_bfloat162 h3 = __floats2bfloat162_rn(v1.z, v1.w);
        uint4 o;
        o.x = *reinterpret_cast<uint32_t*>(&h0);
        o.y = *reinterpret_cast<uint32_t*>(&h1);
        o.z = *reinterpret_cast<uint32_t*>(&h2);
        o.w = *reinterpret_cast<uint32_t*>(&h3);
        ((uint4*)(g_z_bf + (size_t)r * DDIM))[lane] = o;
    }
}

// ---------------------------------------------------------------------------
// Kernel 2: coarse bf16 mma.sync GEMM + per-thread-subset top-2 candidates
// smem: z tile 64KB @0, cb double buffer 2x64KB @65536, e2 2x512B @196608
// ---------------------------------------------------------------------------
#define ZS_OFF 0
#define CB_OFF 65536
#define E2_OFF 196608
#define DSMEM  198656

__device__ __forceinline__ void prefetch_cb(uint32_t sb, int buf, int chunk, int t) {
    const char* csrc = (const char*)(g_cb_bf + (size_t)chunk * 128 * DDIM);
    uint32_t cbase = sb + CB_OFF + (uint32_t)buf * 65536u;
#pragma unroll
    for (int i = 0; i < 16; i++) {
        int id = t + i * 256, r = id >> 5, c = id & 31;
        uint32_t dst = cbase + (uint32_t)r * 512u
                     + ((uint32_t)((c & 24) | ((c ^ r) & 7)) << 4);
        CP_ASYNC16(dst, csrc + (size_t)r * 512 + c * 16);
    }
    if (t < 32) {
        uint32_t dst = sb + E2_OFF + (uint32_t)buf * 512u + (uint32_t)t * 16u;
        CP_ASYNC16(dst, (const char*)(g_e2f + chunk * 128) + t * 16);
    }
}

__global__ void __launch_bounds__(256, 1) vq_coarse_kernel() {
    extern __shared__ __align__(16) char dsm[];
    const uint32_t sb = (smem_u32(dsm) + 1023u) & ~1023u;
    const int t  = threadIdx.x;
    const int l  = t & 31;
    const int wid = t >> 5;
    const int wm = wid >> 2, wn = wid & 3;
    const int m0 = blockIdx.x * 128;

    // z tile + chunk0 (group 0), chunk1 (group 1)
    {
        const char* zsrc = (const char*)(g_z_bf + (size_t)m0 * DDIM);
#pragma unroll
        for (int i = 0; i < 16; i++) {
            int id = t + i * 256, r = id >> 5, c = id & 31;
            uint32_t dst = sb + ZS_OFF + (uint32_t)r * 512u
                         + ((uint32_t)((c & 24) | ((c ^ r) & 7)) << 4);
            CP_ASYNC16(dst, zsrc + (size_t)r * 512 + c * 16);
        }
        prefetch_cb(sb, 0, 0, t);
        CP_COMMIT();
        prefetch_cb(sb, 1, 1, t);
        CP_COMMIT();
    }

    // per-thread constant address components
    uint32_t abase[4], ar7[4];
#pragma unroll
    for (int i = 0; i < 4; i++) {
        int ar = wm * 64 + i * 16 + (l & 15);
        abase[i] = sb + ZS_OFF + (uint32_t)ar * 512u;
        ar7[i]   = (uint32_t)(ar & 7);
    }
    const uint32_t ahalf = (uint32_t)(l >> 4);
    uint32_t boff[2], br7[2];
#pragma unroll
    for (int p = 0; p < 2; p++) {
        int br = wn * 32 + p * 16 + ((l >> 4) & 1) * 8 + (l & 7);
        boff[p] = (uint32_t)br * 512u;
        br7[p]  = (uint32_t)(br & 7);
    }
    const uint32_t bhalf = (uint32_t)((l >> 3) & 1);

    float bd1[8], bd2[8];
    int   bi1[8], bi2[8];
#pragma unroll
    for (int i = 0; i < 8; i++) { bd1[i] = 3.0e38f; bd2[i] = 3.0e38f; bi1[i] = 0; bi2[i] = 0; }

    for (int c = 0; c < NCHUNK; c++) {
        const int s = c & 1;
        if (c < NCHUNK - 1) { CP_WAIT(1); } else { CP_WAIT(0); }
        __syncthreads();

        float acc[4][4][4];
#pragma unroll
        for (int i = 0; i < 4; i++)
#pragma unroll
            for (int j = 0; j < 4; j++)
#pragma unroll
                for (int q = 0; q < 4; q++) acc[i][j][q] = 0.f;

        const uint32_t cbB = sb + CB_OFF + (uint32_t)s * 65536u;
#pragma unroll
        for (int kk = 0; kk < 16; kk++) {
            const uint32_t cA = (uint32_t)(kk * 2) + ahalf;
            const uint32_t swA_hi = (cA & 24u) << 4;
            uint32_t a[4][4];
#pragma unroll
            for (int i = 0; i < 4; i++)
                ldsm_x4(a[i], abase[i] + swA_hi + (((cA ^ ar7[i]) & 7u) << 4));
            const uint32_t cB = (uint32_t)(kk * 2) + bhalf;
            const uint32_t swB_hi = (cB & 24u) << 4;
            uint32_t b[2][4];
#pragma unroll
            for (int p = 0; p < 2; p++)
                ldsm_x4(b[p], cbB + boff[p] + swB_hi + (((cB ^ br7[p]) & 7u) << 4));
#pragma unroll
            for (int i = 0; i < 4; i++)
#pragma unroll
                for (int j = 0; j < 4; j++)
                    mma16816(acc[i][j], a[i], b[j >> 1][(j & 1) * 2], b[j >> 1][(j & 1) * 2 + 1]);
        }

        // epilogue: dist = e2 - 2*dot, per-thread-subset top-2 (ascending code order)
        const uint32_t e2b = sb + E2_OFF + (uint32_t)s * 512u;
        const int nl0 = wn * 32 + (l & 3) * 2;
#pragma unroll
        for (int j = 0; j < 4; j++) {
            const int nl = nl0 + j * 8;
            float e20, e21;
            asm("ld.shared.f32 %0, [%1];" : "=f"(e20) : "r"(e2b + (uint32_t)nl * 4u));
            asm("ld.shared.f32 %0, [%1];" : "=f"(e21) : "r"(e2b + (uint32_t)nl * 4u + 4u));
            const int code0 = c * 128 + nl, code1 = code0 + 1;
#pragma unroll
            for (int i = 0; i < 4; i++) {
                upd(bd1[i*2],   bi1[i*2],   bd2[i*2],   bi2[i*2],
                    fmaf(-2.f, acc[i][j][0], e20), code0);
                upd(bd1[i*2],   bi1[i*2],   bd2[i*2],   bi2[i*2],
                    fmaf(-2.f, acc[i][j][1], e21), code1);
                upd(bd1[i*2+1], bi1[i*2+1], bd2[i*2+1], bi2[i*2+1],
                    fmaf(-2.f, acc[i][j][2], e20), code0);
                upd(bd1[i*2+1], bi1[i*2+1], bd2[i*2+1], bi2[i*2+1],
                    fmaf(-2.f, acc[i][j][3], e21), code1);
            }
        }

        __syncthreads();                     // buf s fully consumed
        if (c + 2 < NCHUNK) { prefetch_cb(sb, s, c + 2, t); CP_COMMIT(); }
    }

    // write candidate indices: 16 threads x top-2 = 32 per row
    const int slot2 = (wn * 4 + (l & 3)) * 2;
#pragma unroll
    for (int i = 0; i < 4; i++) {
#pragma unroll
        for (int h = 0; h < 2; h++) {
            int m = wm * 64 + i * 16 + (l >> 2) + h * 8;
            g_cand[(size_t)(m0 + m) * 32 + slot2]     = bi1[i * 2 + h];
            g_cand[(size_t)(m0 + m) * 32 + slot2 + 1] = bi2[i * 2 + h];
        }
    }
}

// ---------------------------------------------------------------------------
// Kernel 3: exact fp32 rescore of 32 candidates per row (block per row)
// ---------------------------------------------------------------------------
__global__ void __launch_bounds__(128) vq_rescore_kernel(const float* __restrict__ z,
                                                         const float* __restrict__ cb) {
    __shared__ __align__(16) float zs[256];
    __shared__ float sd[32];
    __shared__ int   si[32];
    const int row = blockIdx.x;
    const int t   = threadIdx.x;

    zs[t]       = z[(size_t)row * DDIM + t];
    zs[t + 128] = z[(size_t)row * DDIM + 128 + t];
    __syncthreads();

    const int cand = g_cand[(size_t)row * 32 + (t >> 2)];
    const int sub  = t & 3;
    const float4* cr = (const float4*)(cb + (size_t)cand * DDIM);
    float s = 0.f;
#pragma unroll
    for (int k = 0; k < 16; k++) {
        int d4 = k * 4 + sub;
        float4 cv = cr[d4];
        float4 zv = *(const float4*)(zs + d4 * 4);
        float dx = zv.x - cv.x, dy = zv.y - cv.y, dz = zv.z - cv.z, dw = zv.w - cv.w;
        s += dx * dx + dy * dy + dz * dz + dw * dw;
    }
    s += __shfl_xor_sync(0xffffffffu, s, 1);
    s += __shfl_xor_sync(0xffffffffu, s, 2);
    if (sub == 0) { sd[t >> 2] = s; si[t >> 2] = cand; }
    __syncthreads();
    if (t == 0) {
        float bd = sd[0]; int bi = si[0];
#pragma unroll
        for (int c = 1; c < 32; c++) {
            float d = sd[c]; int ii = si[c];
            if (d < bd || (d == bd && ii < bi)) { bd = d; bi = ii; }
        }
        g_idx[row] = bi;
    }
}

// ---------------------------------------------------------------------------
// Kernel 4: gather z_q, write indices, per-block partial sum of (z_q - z)^2
// ---------------------------------------------------------------------------
__global__ void vq_gather_kernel(const float* __restrict__ z,
                                 const float* __restrict__ cb,
                                 float* __restrict__ out, int out_size) {
    __shared__ float red[256];
    const int t    = threadIdx.x;
    const int base = blockIdx.x * 1024;
    const int e    = base + t * 4;
    const int row  = e >> 8;
    const int col  = e & 255;
    const int code = g_idx[row];

    float4 q  = *(const float4*)(cb + (size_t)code * DDIM + col);
    float4 zv = *(const float4*)(z + e);
    *(float4*)(out + e) = q;

    if (col == 0 && out_size >= OUT_FULL) out[IDX_OFF + row] = (float)code;

    float dx = q.x - zv.x, dy = q.y - zv.y, dz = q.z - zv.z, dw = q.w - zv.w;
    red[t] = dx * dx + dy * dy + dz * dz + dw * dw;
    __syncthreads();
#pragma unroll
    for (int o = 128; o > 0; o >>= 1) {
        if (t < o) red[t] += red[t + o];
        __syncthreads();
    }
    if (t == 0) g_partial[blockIdx.x] = red[0];
}

// ---------------------------------------------------------------------------
// Kernel 5: finalize vq_loss + perplexity
// ---------------------------------------------------------------------------
__global__ void vq_finalize_kernel(const float* __restrict__ ema,
                                   float* __restrict__ out, int out_size) {
    __shared__ float r1[1024], r2[1024];
    const int t = threadIdx.x;

    float s = 0.f;
    for (int i = t; i < GATHER_BLOCKS; i += 1024) s += g_partial[i];
    r1[t] = s;
    __syncthreads();
#pragma unroll
    for (int o = 512; o > 0; o >>= 1) {
        if (t < o) r1[t] += r1[t + o];
        __syncthreads();
    }
    if (t == 0 && out_size >= OUT_FULL) {
        float mse = r1[0] / (float)(NTOT * DDIM);
        out[LOSS_OFF] = 1.25f * mse;
    }
    __syncthreads();

    float sc = 0.f, scl = 0.f;
    for (int k = t; k < KCB; k += 1024) {
        float c = ema[k];
        if (k == 2 || k == 3) c = 0.f;
        c = fmaxf(c, 1e-5f);
        sc  += c;
        scl += c * logf(c);
    }
    r1[t] = sc; r2[t] = scl;
    __syncthreads();
#pragma unroll
    for (int o = 512; o > 0; o >>= 1) {
        if (t < o) { r1[t] += r1[t + o]; r2[t] += r2[t + o]; }
        __syncthreads();
    }
    if (t == 0 && out_size >= OUT_FULL) {
        float T = r1[0] + 1e-5f;
        float entropy = logf(T) * (r1[0] / T) - r2[0] / T;
        out[PPL_OFF] = expf(entropy);
    }
}

// ---------------------------------------------------------------------------
extern "C" void kernel_launch(void* const* d_in, const int* in_sizes, int n_in,
                              void* d_out, int out_size) {
    const float* z   = (const float*)d_in[0];
    const float* cb  = (const float*)d_in[1];
    const float* ema = (const float*)d_in[2];
    float* out = (float*)d_out;

    cudaFuncSetAttribute(vq_coarse_kernel,
                         cudaFuncAttributeMaxDynamicSharedMemorySize, DSMEM);

    vq_convert_kernel<<<(KCB + NTOT) * 32 / 256, 256>>>(z, cb);
    vq_coarse_kernel<<<NTOT / 128, 256, DSMEM>>>();
    vq_rescore_kernel<<<NTOT, 128>>>(z, cb);
    vq_gather_kernel<<<GATHER_BLOCKS, 256>>>(z, cb, out, out_size);
    vq_finalize_kernel<<<1, 1024>>>(ema, out, out_size);
}